// round 13
// baseline (speedup 1.0000x reference)
#include <cuda_runtime.h>
#include <cuda_bf16.h>

#define NRELS 20

// Loads with 256B L2 fill hint (R10 win: fewer, longer DRAM read bursts).
__device__ __forceinline__ float ld_pf(const float* p) {
    float v;
    asm("ld.global.L2::256B.f32 %0, [%1];" : "=f"(v) : "l"(p));
    return v;
}
__device__ __forceinline__ int ld_pf_i(const int* p) {
    int v;
    asm("ld.global.L2::256B.b32 %0, [%1];" : "=r"(v) : "l"(p));
    return v;
}
// Streaming stores: dirty lines marked evict-first -> earlier, batched
// write-backs, less read/write turnaround at the DRAM controller.
__device__ __forceinline__ void st_cs(float* p, float v) {
    asm volatile("st.global.cs.f32 [%0], %1;" :: "l"(p), "f"(v) : "memory");
}

__global__ __launch_bounds__(256, 8)
void alpha_model_pf3(const float* __restrict__ prnt,
                     const float* __restrict__ child,
                     const float* __restrict__ rel_mu,
                     const float* __restrict__ rel_sigma,
                     const float* __restrict__ eps,
                     const float* __restrict__ beta,
                     const int*   __restrict__ rels,
                     float* __restrict__ out,
                     int n)
{
    __shared__ float s_mu[NRELS * 9];
    __shared__ float s_sig[NRELS * 9];
    for (int t = threadIdx.x; t < NRELS * 9; t += blockDim.x) {
        s_mu[t]  = rel_mu[t];
        s_sig[t] = rel_sigma[t];
    }
    __syncthreads();

    int i = blockIdx.x * blockDim.x + threadIdx.x;
    if (i >= n) return;

    // ---- loads (256B fill, coalesced) ----
    int   r = ld_pf_i(&rels[i]);
    float b = ld_pf(&beta[i]);

    float p0 = ld_pf(&prnt[3 * (size_t)i + 0]);
    float p1 = ld_pf(&prnt[3 * (size_t)i + 1]);
    float p2 = ld_pf(&prnt[3 * (size_t)i + 2]);
    float c0 = ld_pf(&child[3 * (size_t)i + 0]);
    float c1 = ld_pf(&child[3 * (size_t)i + 1]);
    float c2 = ld_pf(&child[3 * (size_t)i + 2]);

    float ep[9];
    const float* epp = eps + 9 * (size_t)i;
    #pragma unroll
    for (int k = 0; k < 9; k++) ep[k] = ld_pf(&epp[k]);

    const float* mu = &s_mu[9 * r];
    const float* sg = &s_sig[9 * r];

    // ---- M = mu + sigma*eps ; logits = M @ child ----
    float l0 = fmaf(fmaf(sg[0], ep[0], mu[0]), c0,
               fmaf(fmaf(sg[1], ep[1], mu[1]), c1,
                    fmaf(sg[2], ep[2], mu[2]) * c2));
    float l1 = fmaf(fmaf(sg[3], ep[3], mu[3]), c0,
               fmaf(fmaf(sg[4], ep[4], mu[4]), c1,
                    fmaf(sg[5], ep[5], mu[5]) * c2));
    float l2 = fmaf(fmaf(sg[6], ep[6], mu[6]), c0,
               fmaf(fmaf(sg[7], ep[7], mu[7]), c1,
                    fmaf(sg[8], ep[8], mu[8]) * c2));

    // ---- softmax ----
    float m  = fmaxf(l0, fmaxf(l1, l2));
    float e0 = __expf(l0 - m);
    float e1 = __expf(l1 - m);
    float e2 = __expf(l2 - m);
    float inv_es = __frcp_rn(e0 + e1 + e2);
    float cp0 = e0 * inv_es;
    float cp1 = e1 * inv_es;
    float cp2 = e2 * inv_es;

    // ---- masks (exact-zero semantics) ----
    float child_sum = c0 + c1 + c2;
    float prnt_sum  = p0 + p1 + p2;
    bool child_mask = (child_sum != 0.0f);
    bool copy_mask  = child_mask && (prnt_sum == 0.0f);
    bool alpha_mask = child_mask && (prnt_sum != 0.0f);

    // ---- scale ----
    float z0 = fmaxf(0.01f, p0 + cp0);
    float z1 = fmaxf(0.01f, p1 + cp1);
    float z2 = fmaxf(0.01f, p2 + cp2);
    float inv_zs = __frcp_rn(z0 + z1 + z2);
    z0 *= inv_zs; z1 *= inv_zs; z2 *= inv_zs;
    float entropy = -(z0 * __logf(z0) + z1 * __logf(z1) + z2 * __logf(z2));

    float dot  = p0 * cp0 + p1 * cp1 + p2 * cp2;
    float sqp  = p0 * p0 + p1 * p1 + p2 * p2;
    float sqc  = cp0 * cp0 + cp1 * cp1 + cp2 * cp2;
    float np   = (sqp == 0.0f) ? 0.0f : __fsqrt_rn(sqp);
    float nc   = (sqc == 0.0f) ? 0.0f : __fsqrt_rn(sqc);
    float norm = np * nc;
    norm = (norm == 0.0f) ? 1.0f : norm;
    float cosv = fmaxf(0.01f, dot * __frcp_rn(norm));
    float s = 42.0f * cosv * __frcp_rn(entropy);

    // ---- alpha ----
    float ob = 1.0f - b;
    float a0 = fmaf(ob, p0, b * cp0) * s;
    float a1 = fmaf(ob, p1, b * cp1) * s;
    float a2 = fmaf(ob, p2, b * cp2) * s;

    // ---- streaming stores ----
    size_t N = n;
    st_cs(&out[i], copy_mask ? 1.0f : 0.0f);

    float* ocp = out + N + 3 * (size_t)i;
    st_cs(&ocp[0], copy_mask ? cp0 : 0.0f);
    st_cs(&ocp[1], copy_mask ? cp1 : 0.0f);
    st_cs(&ocp[2], copy_mask ? cp2 : 0.0f);

    st_cs(&out[4 * N + i], alpha_mask ? 1.0f : 0.0f);

    float* oal = out + 5 * N + 3 * (size_t)i;
    st_cs(&oal[0], alpha_mask ? a0 : 0.0f);
    st_cs(&oal[1], alpha_mask ? a1 : 0.0f);
    st_cs(&oal[2], alpha_mask ? a2 : 0.0f);
}

extern "C" void kernel_launch(void* const* d_in, const int* in_sizes, int n_in,
                              void* d_out, int out_size) {
    const float* prnt   = (const float*)d_in[0];
    const float* child  = (const float*)d_in[1];
    const float* rel_mu = (const float*)d_in[2];
    const float* rel_sg = (const float*)d_in[3];
    const float* eps    = (const float*)d_in[4];
    const float* beta   = (const float*)d_in[5];
    const int*   rels   = (const int*)d_in[6];
    float* out = (float*)d_out;

    int n = in_sizes[5];  // beta element count == N
    int threads = 256;
    int blocks = (n + threads - 1) / threads;
    alpha_model_pf3<<<blocks, threads>>>(prnt, child, rel_mu, rel_sg,
                                         eps, beta, rels, out, n);
}

// round 14
// speedup vs baseline: 1.0073x; 1.0073x over previous
#include <cuda_runtime.h>
#include <cuda_bf16.h>

#define NRELS 20
#define PF_DIST 1184   // ~one concurrent CTA wave (148 SMs x 8 CTAs)

// Loads with 256B L2 fill hint (R10 win).
__device__ __forceinline__ float ld_pf(const float* p) {
    float v;
    asm("ld.global.L2::256B.f32 %0, [%1];" : "=f"(v) : "l"(p));
    return v;
}
__device__ __forceinline__ int ld_pf_i(const int* p) {
    int v;
    asm("ld.global.L2::256B.b32 %0, [%1];" : "=r"(v) : "l"(p));
    return v;
}
// Bulk L2 prefetch (no smem destination, no mbarrier; fire-and-forget).
__device__ __forceinline__ void l2_prefetch(const void* p, unsigned bytes) {
    asm volatile("cp.async.bulk.prefetch.L2.global [%0], %1;"
                 :: "l"(p), "r"(bytes));
}

__global__ __launch_bounds__(256, 8)
void alpha_model_pf4(const float* __restrict__ prnt,
                     const float* __restrict__ child,
                     const float* __restrict__ rel_mu,
                     const float* __restrict__ rel_sigma,
                     const float* __restrict__ eps,
                     const float* __restrict__ beta,
                     const int*   __restrict__ rels,
                     float* __restrict__ out,
                     int n)
{
    __shared__ float s_mu[NRELS * 9];
    __shared__ float s_sig[NRELS * 9];
    for (int t = threadIdx.x; t < NRELS * 9; t += blockDim.x) {
        s_mu[t]  = rel_mu[t];
        s_sig[t] = rel_sigma[t];
    }

    // ---- distance prefetch: pull tile (blockIdx.x + PF_DIST) into L2 ----
    if (threadIdx.x == 0) {
        long long pb = (long long)(blockIdx.x + PF_DIST) * 256;
        if (pb + 256 <= n) {
            l2_prefetch(prnt  + 3 * pb, 3 * 256 * 4);
            l2_prefetch(child + 3 * pb, 3 * 256 * 4);
            l2_prefetch(eps   + 9 * pb, 9 * 256 * 4);
            l2_prefetch(beta  + pb,     256 * 4);
            l2_prefetch(rels  + pb,     256 * 4);
        }
    }
    __syncthreads();

    int i = blockIdx.x * blockDim.x + threadIdx.x;
    if (i >= n) return;

    // ---- loads (256B fill, coalesced) ----
    int   r = ld_pf_i(&rels[i]);
    float b = ld_pf(&beta[i]);

    float p0 = ld_pf(&prnt[3 * (size_t)i + 0]);
    float p1 = ld_pf(&prnt[3 * (size_t)i + 1]);
    float p2 = ld_pf(&prnt[3 * (size_t)i + 2]);
    float c0 = ld_pf(&child[3 * (size_t)i + 0]);
    float c1 = ld_pf(&child[3 * (size_t)i + 1]);
    float c2 = ld_pf(&child[3 * (size_t)i + 2]);

    float ep[9];
    const float* epp = eps + 9 * (size_t)i;
    #pragma unroll
    for (int k = 0; k < 9; k++) ep[k] = ld_pf(&epp[k]);

    const float* mu = &s_mu[9 * r];
    const float* sg = &s_sig[9 * r];

    // ---- M = mu + sigma*eps ; logits = M @ child ----
    float l0 = fmaf(fmaf(sg[0], ep[0], mu[0]), c0,
               fmaf(fmaf(sg[1], ep[1], mu[1]), c1,
                    fmaf(sg[2], ep[2], mu[2]) * c2));
    float l1 = fmaf(fmaf(sg[3], ep[3], mu[3]), c0,
               fmaf(fmaf(sg[4], ep[4], mu[4]), c1,
                    fmaf(sg[5], ep[5], mu[5]) * c2));
    float l2 = fmaf(fmaf(sg[6], ep[6], mu[6]), c0,
               fmaf(fmaf(sg[7], ep[7], mu[7]), c1,
                    fmaf(sg[8], ep[8], mu[8]) * c2));

    // ---- softmax ----
    float m  = fmaxf(l0, fmaxf(l1, l2));
    float e0 = __expf(l0 - m);
    float e1 = __expf(l1 - m);
    float e2 = __expf(l2 - m);
    float inv_es = __frcp_rn(e0 + e1 + e2);
    float cp0 = e0 * inv_es;
    float cp1 = e1 * inv_es;
    float cp2 = e2 * inv_es;

    // ---- masks (exact-zero semantics) ----
    float child_sum = c0 + c1 + c2;
    float prnt_sum  = p0 + p1 + p2;
    bool child_mask = (child_sum != 0.0f);
    bool copy_mask  = child_mask && (prnt_sum == 0.0f);
    bool alpha_mask = child_mask && (prnt_sum != 0.0f);

    // ---- scale ----
    float z0 = fmaxf(0.01f, p0 + cp0);
    float z1 = fmaxf(0.01f, p1 + cp1);
    float z2 = fmaxf(0.01f, p2 + cp2);
    float inv_zs = __frcp_rn(z0 + z1 + z2);
    z0 *= inv_zs; z1 *= inv_zs; z2 *= inv_zs;
    float entropy = -(z0 * __logf(z0) + z1 * __logf(z1) + z2 * __logf(z2));

    float dot  = p0 * cp0 + p1 * cp1 + p2 * cp2;
    float sqp  = p0 * p0 + p1 * p1 + p2 * p2;
    float sqc  = cp0 * cp0 + cp1 * cp1 + cp2 * cp2;
    float np   = (sqp == 0.0f) ? 0.0f : __fsqrt_rn(sqp);
    float nc   = (sqc == 0.0f) ? 0.0f : __fsqrt_rn(sqc);
    float norm = np * nc;
    norm = (norm == 0.0f) ? 1.0f : norm;
    float cosv = fmaxf(0.01f, dot * __frcp_rn(norm));
    float s = 42.0f * cosv * __frcp_rn(entropy);

    // ---- alpha ----
    float ob = 1.0f - b;
    float a0 = fmaf(ob, p0, b * cp0) * s;
    float a1 = fmaf(ob, p1, b * cp1) * s;
    float a2 = fmaf(ob, p2, b * cp2) * s;

    // ---- stores (plain: best measured) ----
    size_t N = n;
    out[i] = copy_mask ? 1.0f : 0.0f;

    float* ocp = out + N + 3 * (size_t)i;
    ocp[0] = copy_mask ? cp0 : 0.0f;
    ocp[1] = copy_mask ? cp1 : 0.0f;
    ocp[2] = copy_mask ? cp2 : 0.0f;

    out[4 * N + i] = alpha_mask ? 1.0f : 0.0f;

    float* oal = out + 5 * N + 3 * (size_t)i;
    oal[0] = alpha_mask ? a0 : 0.0f;
    oal[1] = alpha_mask ? a1 : 0.0f;
    oal[2] = alpha_mask ? a2 : 0.0f;
}

extern "C" void kernel_launch(void* const* d_in, const int* in_sizes, int n_in,
                              void* d_out, int out_size) {
    const float* prnt   = (const float*)d_in[0];
    const float* child  = (const float*)d_in[1];
    const float* rel_mu = (const float*)d_in[2];
    const float* rel_sg = (const float*)d_in[3];
    const float* eps    = (const float*)d_in[4];
    const float* beta   = (const float*)d_in[5];
    const int*   rels   = (const int*)d_in[6];
    float* out = (float*)d_out;

    int n = in_sizes[5];  // beta element count == N
    int threads = 256;
    int blocks = (n + threads - 1) / threads;
    alpha_model_pf4<<<blocks, threads>>>(prnt, child, rel_mu, rel_sg,
                                         eps, beta, rels, out, n);
}

// round 17
// speedup vs baseline: 1.0177x; 1.0103x over previous
#include <cuda_runtime.h>
#include <cuda_bf16.h>

#define NRELS 20
#define PF_DIST 1184   // ~one concurrent CTA wave (148 SMs x 8 CTAs)

// Loads with 256B L2 fill hint (R10 win).
__device__ __forceinline__ float ld_pf(const float* p) {
    float v;
    asm("ld.global.L2::256B.f32 %0, [%1];" : "=f"(v) : "l"(p));
    return v;
}
__device__ __forceinline__ int ld_pf_i(const int* p) {
    int v;
    asm("ld.global.L2::256B.b32 %0, [%1];" : "=r"(v) : "l"(p));
    return v;
}
// Bulk L2 prefetch (fire-and-forget).
__device__ __forceinline__ void l2_prefetch(const void* p, unsigned bytes) {
    asm volatile("cp.async.bulk.prefetch.L2.global [%0], %1;"
                 :: "l"(p), "r"(bytes));
}

__global__ __launch_bounds__(256, 8)
void alpha_model_pf5(const float* __restrict__ prnt,
                     const float* __restrict__ child,
                     const float* __restrict__ rel_mu,
                     const float* __restrict__ rel_sigma,
                     const float* __restrict__ eps,
                     const float* __restrict__ beta,
                     const int*   __restrict__ rels,
                     float* __restrict__ out,
                     int n)
{
    __shared__ float s_mu[NRELS * 9];
    __shared__ float s_sig[NRELS * 9];
    for (int t = threadIdx.x; t < NRELS * 9; t += blockDim.x) {
        s_mu[t]  = rel_mu[t];
        s_sig[t] = rel_sigma[t];
    }

    // ---- distance prefetch: even CTAs pull a DOUBLE tile (2x512 edges)
    //      at distance PF_DIST -> half as many, twice-as-long DRAM bursts ----
    if (threadIdx.x == 0 && (blockIdx.x & 1) == 0) {
        long long pb = (long long)(blockIdx.x + PF_DIST) * 256;
        long long pe = pb + 512;                 // two tiles
        if (pe > n) pe = n;
        long long cnt = pe - pb;
        if (cnt > 0) {
            l2_prefetch(prnt  + 3 * pb, (unsigned)(3 * cnt * 4));
            l2_prefetch(child + 3 * pb, (unsigned)(3 * cnt * 4));
            l2_prefetch(eps   + 9 * pb, (unsigned)(9 * cnt * 4));
            l2_prefetch(beta  + pb,     (unsigned)(cnt * 4));
            l2_prefetch(rels  + pb,     (unsigned)(cnt * 4));
        }
    }
    __syncthreads();

    int i = blockIdx.x * blockDim.x + threadIdx.x;
    if (i >= n) return;

    // ---- loads (256B fill, coalesced) ----
    int   r = ld_pf_i(&rels[i]);
    float b = ld_pf(&beta[i]);

    float p0 = ld_pf(&prnt[3 * (size_t)i + 0]);
    float p1 = ld_pf(&prnt[3 * (size_t)i + 1]);
    float p2 = ld_pf(&prnt[3 * (size_t)i + 2]);
    float c0 = ld_pf(&child[3 * (size_t)i + 0]);
    float c1 = ld_pf(&child[3 * (size_t)i + 1]);
    float c2 = ld_pf(&child[3 * (size_t)i + 2]);

    float ep[9];
    const float* epp = eps + 9 * (size_t)i;
    #pragma unroll
    for (int k = 0; k < 9; k++) ep[k] = ld_pf(&epp[k]);

    const float* mu = &s_mu[9 * r];
    const float* sg = &s_sig[9 * r];

    // ---- M = mu + sigma*eps ; logits = M @ child ----
    float l0 = fmaf(fmaf(sg[0], ep[0], mu[0]), c0,
               fmaf(fmaf(sg[1], ep[1], mu[1]), c1,
                    fmaf(sg[2], ep[2], mu[2]) * c2));
    float l1 = fmaf(fmaf(sg[3], ep[3], mu[3]), c0,
               fmaf(fmaf(sg[4], ep[4], mu[4]), c1,
                    fmaf(sg[5], ep[5], mu[5]) * c2));
    float l2 = fmaf(fmaf(sg[6], ep[6], mu[6]), c0,
               fmaf(fmaf(sg[7], ep[7], mu[7]), c1,
                    fmaf(sg[8], ep[8], mu[8]) * c2));

    // ---- softmax ----
    float m  = fmaxf(l0, fmaxf(l1, l2));
    float e0 = __expf(l0 - m);
    float e1 = __expf(l1 - m);
    float e2 = __expf(l2 - m);
    float inv_es = __frcp_rn(e0 + e1 + e2);
    float cp0 = e0 * inv_es;
    float cp1 = e1 * inv_es;
    float cp2 = e2 * inv_es;

    // ---- masks (exact-zero semantics) ----
    float child_sum = c0 + c1 + c2;
    float prnt_sum  = p0 + p1 + p2;
    bool child_mask = (child_sum != 0.0f);
    bool copy_mask  = child_mask && (prnt_sum == 0.0f);
    bool alpha_mask = child_mask && (prnt_sum != 0.0f);

    // ---- scale ----
    float z0 = fmaxf(0.01f, p0 + cp0);
    float z1 = fmaxf(0.01f, p1 + cp1);
    float z2 = fmaxf(0.01f, p2 + cp2);
    float inv_zs = __frcp_rn(z0 + z1 + z2);
    z0 *= inv_zs; z1 *= inv_zs; z2 *= inv_zs;
    float entropy = -(z0 * __logf(z0) + z1 * __logf(z1) + z2 * __logf(z2));

    float dot  = p0 * cp0 + p1 * cp1 + p2 * cp2;
    float sqp  = p0 * p0 + p1 * p1 + p2 * p2;
    float sqc  = cp0 * cp0 + cp1 * cp1 + cp2 * cp2;
    float np   = (sqp == 0.0f) ? 0.0f : __fsqrt_rn(sqp);
    float nc   = (sqc == 0.0f) ? 0.0f : __fsqrt_rn(sqc);
    float norm = np * nc;
    norm = (norm == 0.0f) ? 1.0f : norm;
    float cosv = fmaxf(0.01f, dot * __frcp_rn(norm));
    float s = 42.0f * cosv * __frcp_rn(entropy);

    // ---- alpha ----
    float ob = 1.0f - b;
    float a0 = fmaf(ob, p0, b * cp0) * s;
    float a1 = fmaf(ob, p1, b * cp1) * s;
    float a2 = fmaf(ob, p2, b * cp2) * s;

    // ---- stores (plain: best measured) ----
    size_t N = n;
    out[i] = copy_mask ? 1.0f : 0.0f;

    float* ocp = out + N + 3 * (size_t)i;
    ocp[0] = copy_mask ? cp0 : 0.0f;
    ocp[1] = copy_mask ? cp1 : 0.0f;
    ocp[2] = copy_mask ? cp2 : 0.0f;

    out[4 * N + i] = alpha_mask ? 1.0f : 0.0f;

    float* oal = out + 5 * N + 3 * (size_t)i;
    oal[0] = alpha_mask ? a0 : 0.0f;
    oal[1] = alpha_mask ? a1 : 0.0f;
    oal[2] = alpha_mask ? a2 : 0.0f;
}

extern "C" void kernel_launch(void* const* d_in, const int* in_sizes, int n_in,
                              void* d_out, int out_size) {
    const float* prnt   = (const float*)d_in[0];
    const float* child  = (const float*)d_in[1];
    const float* rel_mu = (const float*)d_in[2];
    const float* rel_sg = (const float*)d_in[3];
    const float* eps    = (const float*)d_in[4];
    const float* beta   = (const float*)d_in[5];
    const int*   rels   = (const int*)d_in[6];
    float* out = (float*)d_out;

    int n = in_sizes[5];  // beta element count == N
    int threads = 256;
    int blocks = (n + threads - 1) / threads;
    alpha_model_pf5<<<blocks, threads>>>(prnt, child, rel_mu, rel_sg,
                                         eps, beta, rels, out, n);
}